// round 2
// baseline (speedup 1.0000x reference)
#include <cuda_runtime.h>
#include <cuda_bf16.h>

// TenHotEncodeLayer: out[n, t, x[n,t,f]] = 1.0 for f in [0,10); all else 0.
// x: [32, 512, 10] int32, out: [32, 512, 5000] float32.
//
// Strategy v2: one CTA per (n,t) row. Build a 5000-bit membership bitmap in
// shared memory (10 atomicOr's), then every thread computes its float4 values
// directly from the bitmap and issues one pure coalesced write stream.
// No second global pass, no global-store ordering barrier, stores batched
// for maximum MLP. This is a single streaming-write kernel at the DRAM
// write roofline.

#define NUM_TOKENS 5000
#define ROW_F4 (NUM_TOKENS / 4)   // 1250
#define NUM_F 10
#define TPB 256
#define BM_WORDS 160              // ceil(5000/32)=157, padded (reads up to 159)

__global__ __launch_bounds__(TPB) void tenhot_kernel(
    const int* __restrict__ x, float4* __restrict__ out)
{
    __shared__ unsigned bm[BM_WORDS];

    const int row = blockIdx.x;
    const int tid = threadIdx.x;

    if (tid < BM_WORDS) bm[tid] = 0u;
    __syncthreads();

    if (tid < NUM_F) {
        int c = __ldg(&x[row * NUM_F + tid]);
        atomicOr(&bm[c >> 5], 1u << (c & 31));
    }
    __syncthreads();

    float4* o = out + (size_t)row * ROW_F4;

    // Compute all 5 chunks first, then batch the stores (front-batched STG
    // for MLP). Chunk c covers columns [4c, 4c+4) -> nibble (c&7)*4 of
    // bitmap word c>>3.
    float4 v[5];
#pragma unroll
    for (int k = 0; k < 5; k++) {
        int c = tid + TPB * k;               // stays < BM_WORDS*8, safe read
        unsigned w = bm[c >> 3];
        unsigned nib = (w >> ((c & 7) * 4)) & 0xFu;
        v[k].x = (nib & 1u) ? 1.0f : 0.0f;
        v[k].y = (nib & 2u) ? 1.0f : 0.0f;
        v[k].z = (nib & 4u) ? 1.0f : 0.0f;
        v[k].w = (nib & 8u) ? 1.0f : 0.0f;
    }

    o[tid]        = v[0];
    o[tid + 256]  = v[1];
    o[tid + 512]  = v[2];
    o[tid + 768]  = v[3];
    if (tid + 1024 < ROW_F4) o[tid + 1024] = v[4];
}

extern "C" void kernel_launch(void* const* d_in, const int* in_sizes, int n_in,
                              void* d_out, int out_size)
{
    const int* x = (const int*)d_in[0];
    float4* out = (float4*)d_out;
    const int rows = in_sizes[0] / NUM_F;   // 32*512 = 16384
    tenhot_kernel<<<rows, TPB>>>(x, out);
}